// round 7
// baseline (speedup 1.0000x reference)
#include <cuda_runtime.h>
#include <cuda_fp16.h>
#include <cstdint>

#define D        256
#define K        1024
#define HW       1024
#define NTOK     32768
#define NBLK     256
#define IDX_OFF  8388608
#define LOSS_OFF 8421376
#define MARGIN   0.12f

// gemm smem layout (bytes). 128 tokens/block, chunks of 32 codes, fp16 single.
#define OFF_A    0          // 128 x 264 halves = 67584
#define OFF_B    67584      // 2 bufs x 16896 (32 codes x 528B)
#define BBUF_SZ  16896
#define OFF_CN   101376     // 4096
#define OFF_STG  105472     // 4096 (128 tok x 2 x float4)
#define SMEM_SZ  109568

__device__ float    g_cnorm[K];
__device__ float    g_partial[NBLK];
__device__ int      g_idx[NTOK];
__device__ int      g_doubt[NTOK];
__device__ int      g_doubt_cnt;
__device__ uint16_t g_cbf16[K * D];

// ---------------- helpers ----------------
__device__ __forceinline__ uint32_t smem_u32(const void* p) {
    uint32_t a;
    asm("{ .reg .u64 t; cvta.to.shared.u64 t, %1; cvt.u32.u64 %0, t; }" : "=r"(a) : "l"(p));
    return a;
}
#define CP_ASYNC16(dst, src) \
    asm volatile("cp.async.cg.shared.global [%0], [%1], 16;" :: "r"(dst), "l"(src) : "memory")
#define CP_COMMIT() asm volatile("cp.async.commit_group;" ::: "memory")
#define CP_WAIT1()  asm volatile("cp.async.wait_group 1;" ::: "memory")
#define CP_WAIT0()  asm volatile("cp.async.wait_group 0;" ::: "memory")

__device__ __forceinline__ void ldsm_x4(uint32_t* r, uint32_t a) {
    asm volatile("ldmatrix.sync.aligned.m8n8.x4.shared.b16 {%0,%1,%2,%3}, [%4];"
        : "=r"(r[0]), "=r"(r[1]), "=r"(r[2]), "=r"(r[3]) : "r"(a));
}
__device__ __forceinline__ void mma_fp16(float* c, const uint32_t* a, const uint32_t* b) {
    asm volatile(
        "mma.sync.aligned.m16n8k16.row.col.f32.f16.f16.f32 "
        "{%0,%1,%2,%3}, {%4,%5,%6,%7}, {%8,%9}, {%0,%1,%2,%3};"
        : "+f"(c[0]), "+f"(c[1]), "+f"(c[2]), "+f"(c[3])
        : "r"(a[0]), "r"(a[1]), "r"(a[2]), "r"(a[3]), "r"(b[0]), "r"(b[1]));
}
__device__ __forceinline__ bool better(float v, int i, float V, int I) {
    return v < V || (v == V && i < I);
}

// ---------------- Kernel 0: codebook -> fp16 ----------------
__global__ void prep_kernel(const float* __restrict__ cb) {
    int i = blockIdx.x * 256 + threadIdx.x;
    g_cbf16[i] = __half_as_ushort(__float2half(cb[i]));
}

// ---------------- Kernel 1: cnorm + counter reset ----------------
__global__ void cnorm_kernel(const float* __restrict__ cb) {
    if (blockIdx.x == 0 && threadIdx.x == 0) g_doubt_cnt = 0;
    int k = blockIdx.x * 8 + (threadIdx.x >> 5);
    int lane = threadIdx.x & 31;
    const float* row = cb + k * D;
    float s = 0.f;
#pragma unroll
    for (int d = lane; d < D; d += 32) { float v = row[d]; s = fmaf(v, v, s); }
#pragma unroll
    for (int o = 16; o; o >>= 1) s += __shfl_xor_sync(~0u, s, o);
    if (lane == 0) g_cnorm[k] = s;
}

// ---------------- Kernel 2: fp16 HMMA GEMM + top-2 argmin ----------------
// 256 blocks x 128 tokens, 2 CTAs/SM (single wave). Warp tile 32x16, chunks of 32 codes.
__global__ __launch_bounds__(256, 2) void vq_gemm(const float* __restrict__ z) {
    extern __shared__ char sm[];
    const uint32_t su = smem_u32(sm);
    const int t = threadIdx.x, w = t >> 5, lane = t & 31;
    const int g = lane >> 2, p = lane & 3;
    const int mw = w >> 1, nw = w & 1;
    const int n0 = blockIdx.x * 128;
    const int b = n0 >> 10, hw0 = n0 & 1023;
    const float* zb = z + b * (D * HW) + hw0;

    uint16_t* sA  = (uint16_t*)(sm + OFF_A);
    float*    scn = (float*)(sm + OFF_CN);
    float4*   stg = (float4*)(sm + OFF_STG);

    // ---- A: load z coalesced (128 tokens x 256 dims) -> fp16 smem [tok][dim] ----
#pragma unroll
    for (int j = 0; j < 32; j++) {
        int l = j * 256 + t;
        int d = l >> 5, f4 = l & 31;
        float4 v = *(const float4*)(zb + d * HW + f4 * 4);
        float vv[4] = {v.x, v.y, v.z, v.w};
#pragma unroll
        for (int q = 0; q < 4; q++)
            sA[(f4 * 4 + q) * 264 + d] = __half_as_ushort(__float2half(vv[q]));
    }
    for (int c = t; c < K; c += 256) scn[c] = g_cnorm[c];

    // prefetch B chunk 0: 32 codes x 512B = 1024 cp16, 4 per thread
#pragma unroll
    for (int j = 0; j < 4; j++) {
        int s = j * 256 + t;
        int code = s >> 5, seg = s & 31;
        uint32_t dst = su + OFF_B + code * 528 + seg * 16;
        CP_ASYNC16(dst, (const char*)g_cbf16 + code * 512 + seg * 16);
    }
    CP_COMMIT();
    __syncthreads();

    // ldmatrix lane addresses
    const int l8 = lane & 7, mat = lane >> 3;
    const uint32_t aAddr = su + OFF_A
        + (uint32_t)((mw * 32 + l8 + (mat & 1) * 8) * 528 + (mat >> 1) * 16);
    const uint32_t boff = (uint32_t)((nw * 16 + (mat >> 1) * 8 + l8) * 528 + (mat & 1) * 16);

    float rv1[2][2], rv2[2][2];
    int   ri1[2][2], ri2[2][2];
#pragma unroll
    for (int mt = 0; mt < 2; mt++)
#pragma unroll
        for (int rr = 0; rr < 2; rr++) {
            rv1[mt][rr] = 3.4e38f; rv2[mt][rr] = 3.4e38f;
            ri1[mt][rr] = 0; ri2[mt][rr] = 0;
        }

    for (int nc = 0; nc < 32; nc++) {
        if (nc < 31) {
            int nn = nc + 1, buf = nn & 1;
#pragma unroll
            for (int j = 0; j < 4; j++) {
                int s = j * 256 + t;
                int code = s >> 5, seg = s & 31;
                uint32_t dst = su + OFF_B + buf * BBUF_SZ + code * 528 + seg * 16;
                CP_ASYNC16(dst, (const char*)g_cbf16 + (nn * 32 + code) * 512 + seg * 16);
            }
            CP_COMMIT();
            CP_WAIT1();
        } else {
            CP_WAIT0();
        }
        __syncthreads();

        const uint32_t bAddr = su + OFF_B + (uint32_t)(nc & 1) * BBUF_SZ + boff;

        float acc[2][2][4];
#pragma unroll
        for (int mt = 0; mt < 2; mt++)
#pragma unroll
            for (int nt = 0; nt < 2; nt++)
#pragma unroll
                for (int q = 0; q < 4; q++) acc[mt][nt][q] = 0.f;

        // fragment double-buffer across ks
        uint32_t ah[2][2][4], bb[2][4];
        ldsm_x4(ah[0][0], aAddr);
        ldsm_x4(ah[0][1], aAddr + 16 * 528);
        ldsm_x4(bb[0], bAddr);

#pragma unroll
        for (int ks = 0; ks < 16; ks++) {
            const int cur = ks & 1, nxt = cur ^ 1;
            if (ks < 15) {
                uint32_t ko = (uint32_t)((ks + 1) * 32);
                ldsm_x4(ah[nxt][0], aAddr + ko);
                ldsm_x4(ah[nxt][1], aAddr + 16 * 528 + ko);
                ldsm_x4(bb[nxt], bAddr + ko);
            }
#pragma unroll
            for (int mt = 0; mt < 2; mt++)
#pragma unroll
                for (int nt = 0; nt < 2; nt++)
                    mma_fp16(acc[mt][nt], ah[cur][mt], &bb[cur][nt * 2]);
        }

        // fold into running top-2 (codes ascending per thread)
#pragma unroll
        for (int nt = 0; nt < 2; nt++)
#pragma unroll
            for (int q = 0; q < 2; q++) {
                int c = nc * 32 + nw * 16 + nt * 8 + 2 * p + q;
                float cn = scn[c];
#pragma unroll
                for (int mt = 0; mt < 2; mt++)
#pragma unroll
                    for (int rr = 0; rr < 2; rr++) {
                        float v = fmaf(-2.f, acc[mt][nt][rr * 2 + q], cn);
                        if (v < rv1[mt][rr]) {
                            rv2[mt][rr] = rv1[mt][rr]; ri2[mt][rr] = ri1[mt][rr];
                            rv1[mt][rr] = v;           ri1[mt][rr] = c;
                        } else if (v < rv2[mt][rr]) {
                            rv2[mt][rr] = v;           ri2[mt][rr] = c;
                        }
                    }
            }
        __syncthreads();
    }

    // ---- merge top-2 across p lanes (xor 1, 2) ----
#pragma unroll
    for (int o = 1; o <= 2; o <<= 1) {
#pragma unroll
        for (int mt = 0; mt < 2; mt++)
#pragma unroll
            for (int rr = 0; rr < 2; rr++) {
                float ov1 = __shfl_xor_sync(~0u, rv1[mt][rr], o);
                int   oi1 = __shfl_xor_sync(~0u, ri1[mt][rr], o);
                float ov2 = __shfl_xor_sync(~0u, rv2[mt][rr], o);
                int   oi2 = __shfl_xor_sync(~0u, ri2[mt][rr], o);
                if (better(ov1, oi1, rv1[mt][rr], ri1[mt][rr])) {
                    if (better(rv1[mt][rr], ri1[mt][rr], ov2, oi2)) {
                        rv2[mt][rr] = rv1[mt][rr]; ri2[mt][rr] = ri1[mt][rr];
                    } else { rv2[mt][rr] = ov2; ri2[mt][rr] = oi2; }
                    rv1[mt][rr] = ov1; ri1[mt][rr] = oi1;
                } else if (better(ov1, oi1, rv2[mt][rr], ri2[mt][rr])) {
                    rv2[mt][rr] = ov1; ri2[mt][rr] = oi1;
                }
            }
    }
    if (p == 0) {
#pragma unroll
        for (int mt = 0; mt < 2; mt++)
#pragma unroll
            for (int rr = 0; rr < 2; rr++) {
                int tok = mw * 32 + mt * 16 + rr * 8 + g;
                stg[tok * 2 + nw] = make_float4(rv1[mt][rr], __int_as_float(ri1[mt][rr]),
                                                rv2[mt][rr], __int_as_float(ri2[mt][rr]));
            }
    }
    __syncthreads();

    if (t < 128) {
        float4 a = stg[t * 2], bq = stg[t * 2 + 1];
        float v1 = a.x, v2 = a.z; int i1 = __float_as_int(a.y), i2 = __float_as_int(a.w);
        float w1 = bq.x, w2 = bq.z; int j1 = __float_as_int(bq.y), j2 = __float_as_int(bq.w);
        float fv1, fv2; int fi1;
        if (better(w1, j1, v1, i1)) {
            fv1 = w1; fi1 = j1;
            fv2 = better(v1, i1, w2, j2) ? v1 : w2;
        } else {
            fv1 = v1; fi1 = i1;
            fv2 = better(w1, j1, v2, i2) ? w1 : v2;
        }
        g_idx[n0 + t] = fi1;
        if (fv2 - fv1 < MARGIN) {
            int s = atomicAdd(&g_doubt_cnt, 1);
            g_doubt[s] = n0 + t;
        }
    }
}

// ---------------- Kernel 3: exact fp32 full-scan rescue ----------------
__global__ __launch_bounds__(256) void rescue_kernel(const float* __restrict__ z,
                                                     const float* __restrict__ cb) {
    __shared__ float sz[D];
    __shared__ float swv[8];
    __shared__ int   swi[8];
    const int t = threadIdx.x, w = t >> 5, lane = t & 31;
    const int cnt = g_doubt_cnt;
    for (int e = blockIdx.x; e < cnt; e += gridDim.x) {
        int n = g_doubt[e];
        int bb = n >> 10, hw = n & 1023;
        sz[t] = z[bb * (D * HW) + t * HW + hw];
        __syncthreads();
        float bv = 3.4e38f; int bi = 0;
        for (int c = w; c < K; c += 8) {
            const float* row = cb + c * D;
            float dsum = 0.f;
#pragma unroll
            for (int d = lane; d < D; d += 32) dsum = fmaf(sz[d], __ldg(row + d), dsum);
#pragma unroll
            for (int o = 16; o; o >>= 1) dsum += __shfl_xor_sync(~0u, dsum, o);
            float v = fmaf(-2.f, dsum, g_cnorm[c]);
            if (v < bv) { bv = v; bi = c; }   // c ascending per warp
        }
        if (lane == 0) { swv[w] = bv; swi[w] = bi; }
        __syncthreads();
        if (t == 0) {
            float m = swv[0]; int mi = swi[0];
#pragma unroll
            for (int i = 1; i < 8; i++)
                if (swv[i] < m || (swv[i] == m && swi[i] < mi)) { m = swv[i]; mi = swi[i]; }
            g_idx[n] = mi;
        }
        __syncthreads();
    }
}

// ---------------- Kernel 4: outputs ----------------
__global__ __launch_bounds__(256) void vq_out(const float* __restrict__ z,
                                              const float* __restrict__ cb,
                                              float* __restrict__ out) {
    __shared__ int rowIdx[128];
    __shared__ float wsum[8];
    const int t = threadIdx.x;
    const int n0 = blockIdx.x * 128;
    const int b = n0 >> 10, hw0 = n0 & 1023;
    if (t < 128) {
        int idx = g_idx[n0 + t];
        rowIdx[t] = idx;
        out[IDX_OFF + n0 + t] = (float)idx;
    }
    __syncthreads();
    const float* zb = z + b * (D * HW) + hw0;
    float* outz = out + b * (D * HW) + hw0;
    float lsum = 0.f;
#pragma unroll 4
    for (int j = 0; j < 128; j++) {
        int l = j * 256 + t;
        int i = l & 127, d = l >> 7;
        float ze = zb[d * HW + i];
        float zq = __ldg(cb + rowIdx[i] * D + d);
        float diff = zq - ze;
        outz[d * HW + i] = ze + diff;
        lsum = fmaf(diff, diff, lsum);
    }
#pragma unroll
    for (int o = 16; o; o >>= 1) lsum += __shfl_xor_sync(~0u, lsum, o);
    if ((t & 31) == 0) wsum[t >> 5] = lsum;
    __syncthreads();
    if (t == 0) {
        float s = 0.f;
#pragma unroll
        for (int ww = 0; ww < 8; ww++) s += wsum[ww];
        g_partial[blockIdx.x] = s;
    }
}

__global__ void finalize_kernel(float* __restrict__ out) {
    float s = 0.f;
    for (int i = 0; i < NBLK; i++) s += g_partial[i];
    float mean = s / 8388608.f;
    out[LOSS_OFF] = mean + 0.25f * mean;
}

// ---------------------------------------------------------------------------
extern "C" void kernel_launch(void* const* d_in, const int* in_sizes, int n_in,
                              void* d_out, int out_size) {
    const float* z  = (const float*)d_in[0];
    const float* cb = (const float*)d_in[1];
    float* out = (float*)d_out;

    cudaFuncSetAttribute(vq_gemm, cudaFuncAttributeMaxDynamicSharedMemorySize, SMEM_SZ);

    prep_kernel<<<1024, 256>>>(cb);
    cnorm_kernel<<<128, 256>>>(cb);
    vq_gemm<<<NBLK, 256, SMEM_SZ>>>(z);
    rescue_kernel<<<128, 256>>>(z, cb);
    vq_out<<<NBLK, 256>>>(z, cb, out);
    finalize_kernel<<<1, 1>>>(out);
}